// round 5
// baseline (speedup 1.0000x reference)
#include <cuda_runtime.h>
#include <cstdint>
#include <cstddef>

// Problem constants
constexpr int B   = 65536;
constexpr int T   = 30;
constexpr int H   = 64;
constexpr int G   = 256;   // 4*H, gate order i,f,g,o
constexpr int IN0 = 9;

constexpr int TPB0 = 256;  // layer0 threads (samples) per CTA
constexpr int TPB1 = 128;  // layer1 threads (samples) per CTA

// Scratch: layer0 outputs, layout [t][k][s]  (coalesced for both writer & reader)
__device__ float g_out0[(size_t)T * H * B];

// ---------------- f32x2 helpers (FFMA2 path, sm_100+) ----------------
__device__ __forceinline__ unsigned long long pack2(float a, float b) {
    unsigned long long r;
    asm("mov.b64 %0, {%1, %2};" : "=l"(r) : "f"(a), "f"(b));
    return r;
}
__device__ __forceinline__ void unpack2(unsigned long long v, float& a, float& b) {
    asm("mov.b64 {%0, %1}, %2;" : "=f"(a), "=f"(b) : "l"(v));
}
__device__ __forceinline__ unsigned long long fma2(unsigned long long a,
                                                   unsigned long long b,
                                                   unsigned long long c) {
    unsigned long long d;
    asm("fma.rn.f32x2 %0, %1, %2, %3;" : "=l"(d) : "l"(a), "l"(b), "l"(c));
    return d;
}

// Accurate-enough nonlinearities (~1e-6 rel err), cheap (1 MUFU.EX2 + 1 fast div)
__device__ __forceinline__ float sigf(float x) {
    return __fdividef(1.f, 1.f + __expf(-x));
}
__device__ __forceinline__ float tanh_(float x) {
    return __fdividef(2.f, 1.f + __expf(-2.f * x)) - 1.f;
}

// =====================================================================
// Layer 0: x[B][T][9] -> g_out0[t][k][s]
// =====================================================================
__global__ void __launch_bounds__(TPB0) lstm_layer0(
    const float* __restrict__ x,
    const float* __restrict__ Wih,   // [256][9]
    const float* __restrict__ Whh,   // [256][64]
    const float* __restrict__ bih,
    const float* __restrict__ bhh)
{
    extern __shared__ float sm[];
    float* s_wih  = sm;                       // [9][256]  transposed
    float* s_whh  = s_wih + IN0 * G;          // [64][256] transposed
    float* s_bias = s_whh + H * G;            // [256]
    float* s_h0   = s_bias + G;               // [64][TPB0]
    float* s_h1   = s_h0 + H * TPB0;          // [64][TPB0]

    const int tid = threadIdx.x;

    for (int idx = tid; idx < G * IN0; idx += TPB0) {
        int g = idx / IN0, i = idx - g * IN0;
        s_wih[i * G + g] = Wih[idx];
    }
    for (int idx = tid; idx < G * H; idx += TPB0) {
        int g = idx >> 6, k = idx & 63;
        s_whh[k * G + g] = Whh[idx];
    }
    for (int idx = tid; idx < G; idx += TPB0) s_bias[idx] = bih[idx] + bhh[idx];
#pragma unroll
    for (int k = 0; k < H; k++) s_h0[k * TPB0 + tid] = 0.f;
    __syncthreads();

    const int s = blockIdx.x * TPB0 + tid;
    const float* xp = x + (size_t)s * (T * IN0);

    float c[H];
#pragma unroll
    for (int k = 0; k < H; k++) c[k] = 0.f;

    float* hcur = s_h0;
    float* hnew = s_h1;

    for (int t = 0; t < T; t++) {
        float xr[IN0];
#pragma unroll
        for (int i = 0; i < IN0; i++) xr[i] = xp[t * IN0 + i];

#pragma unroll
        for (int jb = 0; jb < 8; jb++) {
            const int g0 = jb * 8;
            unsigned long long acc[16];
#pragma unroll
            for (int q = 0; q < 4; q++) {
                const ulonglong2* bp =
                    (const ulonglong2*)&s_bias[q * H + g0];
                ulonglong2 b0 = bp[0], b1 = bp[1];
                acc[q * 4 + 0] = b0.x; acc[q * 4 + 1] = b0.y;
                acc[q * 4 + 2] = b1.x; acc[q * 4 + 3] = b1.y;
            }
            // input projection (9 terms)
#pragma unroll
            for (int i = 0; i < IN0; i++) {
                unsigned long long x2 = pack2(xr[i], xr[i]);
                const float* wrow = &s_wih[i * G + g0];
#pragma unroll
                for (int q = 0; q < 4; q++) {
                    const ulonglong2* wv = (const ulonglong2*)&wrow[q * H];
                    ulonglong2 w0 = wv[0], w1 = wv[1];
                    acc[q * 4 + 0] = fma2(w0.x, x2, acc[q * 4 + 0]);
                    acc[q * 4 + 1] = fma2(w0.y, x2, acc[q * 4 + 1]);
                    acc[q * 4 + 2] = fma2(w1.x, x2, acc[q * 4 + 2]);
                    acc[q * 4 + 3] = fma2(w1.y, x2, acc[q * 4 + 3]);
                }
            }
            // recurrent part (64 terms)
#pragma unroll 2
            for (int k = 0; k < H; k++) {
                float hk = hcur[k * TPB0 + tid];
                unsigned long long h2 = pack2(hk, hk);
                const float* wrow = &s_whh[k * G + g0];
#pragma unroll
                for (int q = 0; q < 4; q++) {
                    const ulonglong2* wv = (const ulonglong2*)&wrow[q * H];
                    ulonglong2 w0 = wv[0], w1 = wv[1];
                    acc[q * 4 + 0] = fma2(w0.x, h2, acc[q * 4 + 0]);
                    acc[q * 4 + 1] = fma2(w0.y, h2, acc[q * 4 + 1]);
                    acc[q * 4 + 2] = fma2(w1.x, h2, acc[q * 4 + 2]);
                    acc[q * 4 + 3] = fma2(w1.y, h2, acc[q * 4 + 3]);
                }
            }
            // gate nonlinearities + state update for 8 units
#pragma unroll
            for (int u = 0; u < 8; u++) {
                const int p = u >> 1, lane = u & 1;
                float ga[4];
#pragma unroll
                for (int q = 0; q < 4; q++) {
                    float lo, hi;
                    unpack2(acc[q * 4 + p], lo, hi);
                    ga[q] = lane ? hi : lo;
                }
                float iv = sigf(ga[0]);
                float fv = sigf(ga[1]);
                float gv = tanh_(ga[2]);
                float ov = sigf(ga[3]);
                const int j = g0 + u;
                float cc = fv * c[j] + iv * gv;
                c[j] = cc;
                float hv = ov * tanh_(cc);
                hnew[j * TPB0 + tid] = hv;
                g_out0[((size_t)t * H + j) * B + s] = hv;
            }
        }
        float* tmp = hcur; hcur = hnew; hnew = tmp;
    }
}

// =====================================================================
// Layer 1: g_out0 -> LSTM -> LayerNorm(h_T) -> out[B][64]
// =====================================================================
__global__ void __launch_bounds__(TPB1) lstm_layer1(
    const float* __restrict__ Wih,   // [256][64]
    const float* __restrict__ Whh,   // [256][64]
    const float* __restrict__ bih,
    const float* __restrict__ bhh,
    const float* __restrict__ gamma,
    const float* __restrict__ beta,
    float* __restrict__ out)
{
    extern __shared__ float sm[];
    float* s_wih  = sm;                       // [64][256]
    float* s_whh  = s_wih + H * G;            // [64][256]
    float* s_bias = s_whh + H * G;            // [256]
    float* s_x    = s_bias + G;               // [64][TPB1]
    float* s_h0   = s_x + H * TPB1;           // [64][TPB1]
    float* s_h1   = s_h0 + H * TPB1;          // [64][TPB1]

    const int tid = threadIdx.x;

    for (int idx = tid; idx < G * H; idx += TPB1) {
        int g = idx >> 6, k = idx & 63;
        s_wih[k * G + g] = Wih[idx];
        s_whh[k * G + g] = Whh[idx];
    }
    for (int idx = tid; idx < G; idx += TPB1) s_bias[idx] = bih[idx] + bhh[idx];
#pragma unroll
    for (int k = 0; k < H; k++) s_h0[k * TPB1 + tid] = 0.f;
    __syncthreads();

    const int s = blockIdx.x * TPB1 + tid;

    float c[H];
#pragma unroll
    for (int k = 0; k < H; k++) c[k] = 0.f;

    float* hcur = s_h0;
    float* hnew = s_h1;

    for (int t = 0; t < T; t++) {
        // stage this timestep's layer-0 output (coalesced LDG)
        const float* src = g_out0 + (size_t)t * H * B + s;
#pragma unroll 8
        for (int k = 0; k < H; k++) s_x[k * TPB1 + tid] = src[(size_t)k * B];

#pragma unroll
        for (int jb = 0; jb < 8; jb++) {
            const int g0 = jb * 8;
            unsigned long long acc[16];
#pragma unroll
            for (int q = 0; q < 4; q++) {
                const ulonglong2* bp =
                    (const ulonglong2*)&s_bias[q * H + g0];
                ulonglong2 b0 = bp[0], b1 = bp[1];
                acc[q * 4 + 0] = b0.x; acc[q * 4 + 1] = b0.y;
                acc[q * 4 + 2] = b1.x; acc[q * 4 + 3] = b1.y;
            }
#pragma unroll 2
            for (int k = 0; k < H; k++) {
                float xk = s_x[k * TPB1 + tid];
                float hk = hcur[k * TPB1 + tid];
                unsigned long long x2 = pack2(xk, xk);
                unsigned long long h2 = pack2(hk, hk);
                const float* wi = &s_wih[k * G + g0];
                const float* wh = &s_whh[k * G + g0];
#pragma unroll
                for (int q = 0; q < 4; q++) {
                    const ulonglong2* wiv = (const ulonglong2*)&wi[q * H];
                    const ulonglong2* whv = (const ulonglong2*)&wh[q * H];
                    ulonglong2 a0 = wiv[0], a1 = wiv[1];
                    ulonglong2 b0 = whv[0], b1 = whv[1];
                    acc[q * 4 + 0] = fma2(a0.x, x2, acc[q * 4 + 0]);
                    acc[q * 4 + 1] = fma2(a0.y, x2, acc[q * 4 + 1]);
                    acc[q * 4 + 2] = fma2(a1.x, x2, acc[q * 4 + 2]);
                    acc[q * 4 + 3] = fma2(a1.y, x2, acc[q * 4 + 3]);
                    acc[q * 4 + 0] = fma2(b0.x, h2, acc[q * 4 + 0]);
                    acc[q * 4 + 1] = fma2(b0.y, h2, acc[q * 4 + 1]);
                    acc[q * 4 + 2] = fma2(b1.x, h2, acc[q * 4 + 2]);
                    acc[q * 4 + 3] = fma2(b1.y, h2, acc[q * 4 + 3]);
                }
            }
#pragma unroll
            for (int u = 0; u < 8; u++) {
                const int p = u >> 1, lane = u & 1;
                float ga[4];
#pragma unroll
                for (int q = 0; q < 4; q++) {
                    float lo, hi;
                    unpack2(acc[q * 4 + p], lo, hi);
                    ga[q] = lane ? hi : lo;
                }
                float iv = sigf(ga[0]);
                float fv = sigf(ga[1]);
                float gv = tanh_(ga[2]);
                float ov = sigf(ga[3]);
                const int j = g0 + u;
                float cc = fv * c[j] + iv * gv;
                c[j] = cc;
                hnew[j * TPB1 + tid] = ov * tanh_(cc);
            }
        }
        float* tmp = hcur; hcur = hnew; hnew = tmp;
    }

    // LayerNorm over final hidden state (64 values, thread-local)
    float sum = 0.f;
#pragma unroll
    for (int k = 0; k < H; k++) sum += hcur[k * TPB1 + tid];
    float mean = sum * (1.f / 64.f);
    float vs = 0.f;
#pragma unroll
    for (int k = 0; k < H; k++) {
        float d = hcur[k * TPB1 + tid] - mean;
        vs += d * d;
    }
    float rstd = rsqrtf(vs * (1.f / 64.f) + 1e-5f);
#pragma unroll
    for (int k = 0; k < H; k++) {
        float v = (hcur[k * TPB1 + tid] - mean) * rstd;
        out[(size_t)s * H + k] = v * gamma[k] + beta[k];
    }
}

// =====================================================================
extern "C" void kernel_launch(void* const* d_in, const int* in_sizes, int n_in,
                              void* d_out, int out_size) {
    (void)in_sizes; (void)n_in; (void)out_size;
    const float* x     = (const float*)d_in[0];
    const float* Wih0  = (const float*)d_in[1];
    const float* Whh0  = (const float*)d_in[2];
    const float* bih0  = (const float*)d_in[3];
    const float* bhh0  = (const float*)d_in[4];
    const float* Wih1  = (const float*)d_in[5];
    const float* Whh1  = (const float*)d_in[6];
    const float* bih1  = (const float*)d_in[7];
    const float* bhh1  = (const float*)d_in[8];
    const float* gamma = (const float*)d_in[9];
    const float* beta  = (const float*)d_in[10];
    float* out = (float*)d_out;

    const size_t smem0 =
        (size_t)(IN0 * G + H * G + G + 2 * H * TPB0) * sizeof(float); // 206,848 B
    const size_t smem1 =
        (size_t)(2 * H * G + G + 3 * H * TPB1) * sizeof(float);       // 230,400 B

    cudaFuncSetAttribute(lstm_layer0, cudaFuncAttributeMaxDynamicSharedMemorySize,
                         (int)smem0);
    cudaFuncSetAttribute(lstm_layer1, cudaFuncAttributeMaxDynamicSharedMemorySize,
                         (int)smem1);

    lstm_layer0<<<B / TPB0, TPB0, smem0>>>(x, Wih0, Whh0, bih0, bhh0);
    lstm_layer1<<<B / TPB1, TPB1, smem1>>>(Wih1, Whh1, bih1, bhh1, gamma, beta, out);
}

// round 7
// speedup vs baseline: 2.9023x; 2.9023x over previous
#include <cuda_runtime.h>
#include <cuda_fp16.h>
#include <cstdint>
#include <cstddef>

constexpr int B  = 65536;
constexpr int T  = 30;
constexpr int MT = 128;          // samples per CTA
constexpr int THREADS = 256;     // 8 warps: 2 (m) x 4 (n)

// ---------------- Kernel0 smem offsets (bytes) ----------------
constexpr int SM0_X     = 0;       // [128 rows][stride 112B]  K=48 combined x tile
constexpr int SM0_WIH   = 14336;   // [256 n][stride 112B]     combined Wih0 hi/lo + bias
constexpr int SM0_HH    = 43008;   // [128][128B] swizzled     h0 hi
constexpr int SM0_HL    = 59392;   // h0 lo
constexpr int SM0_WHH_H = 75776;   // [256][128B] swizzled
constexpr int SM0_WHH_L = 108544;
constexpr int SM0_TOTAL = 141312;

// ---------------- Kernel1 smem offsets ----------------
constexpr int SM1_XH    = 0;       // staged h0 hi [128][128B] swz
constexpr int SM1_XL    = 16384;
constexpr int SM1_H1H   = 32768;   // h1 hi
constexpr int SM1_H1L   = 49152;
constexpr int SM1_WIH_H = 65536;   // [256][128B] swz
constexpr int SM1_WIH_L = 98304;
constexpr int SM1_WHH_H = 131072;
constexpr int SM1_WHH_L = 163840;
constexpr int SM1_BIAS  = 196608;  // 256 f32, indexed by reordered gate col
constexpr int SM1_TOTAL = 197632;

// scratch: layer0 h (hi/lo fp16), [t][sample][8 x 16B chunks], coalesced both ways
__device__ uint4 g_h0hi[(size_t)T * B * 8];
__device__ uint4 g_h0lo[(size_t)T * B * 8];

// ---------------- helpers ----------------
__device__ __forceinline__ uint32_t smem_u32(const void* p) {
    uint32_t a;
    asm("{ .reg .u64 t; cvta.to.shared.u64 t, %1; cvt.u32.u64 %0, t; }"
        : "=r"(a) : "l"(p));
    return a;
}
__device__ __forceinline__ float sigf(float x) {
    return __fdividef(1.f, 1.f + __expf(-x));
}
__device__ __forceinline__ float tanh_(float x) {
    return __fdividef(2.f, 1.f + __expf(-2.f * x)) - 1.f;
}
__device__ __forceinline__ uint32_t f2h2(float a, float b) {
    __half2 h = __floats2half2_rn(a, b);
    return *reinterpret_cast<uint32_t*>(&h);
}

__device__ __forceinline__ void ldsm4(uint32_t (&r)[4], uint32_t addr) {
    asm volatile("ldmatrix.sync.aligned.m8n8.x4.shared.b16 {%0,%1,%2,%3}, [%4];"
        : "=r"(r[0]), "=r"(r[1]), "=r"(r[2]), "=r"(r[3]) : "r"(addr));
}
__device__ __forceinline__ void mma_f16(float (&d)[4], const uint32_t (&a)[4],
                                        uint32_t b0, uint32_t b1) {
    asm volatile(
        "mma.sync.aligned.m16n8k16.row.col.f32.f16.f16.f32 "
        "{%0,%1,%2,%3},{%4,%5,%6,%7},{%8,%9},{%0,%1,%2,%3};"
        : "+f"(d[0]), "+f"(d[1]), "+f"(d[2]), "+f"(d[3])
        : "r"(a[0]), "r"(a[1]), "r"(a[2]), "r"(a[3]), "r"(b0), "r"(b1));
}

// One GEMM group: A tile vs NB (1|2) B tiles, accumulating into acc[4][8][4].
// KS k16-steps; strides in bytes; SW = XOR-16B-chunk swizzle for 128B-stride tiles.
template<int KS, int SA, int SB, bool SWA, bool SWB, int NB>
__device__ __forceinline__ void gemm_acc(uint32_t aBase, uint32_t bBase0, uint32_t bBase1,
                                         float (&acc)[4][8][4],
                                         int mrow0, int ncol0, int lane)
{
    const int grp = lane >> 3, j = lane & 7;
    const int arow_off = ((grp & 1) << 3) + j;
    const int ach_off  = grp >> 1;
    const int brow_off = ((grp >> 1) << 3) + j;
    const int bch_off  = grp & 1;
#pragma unroll
    for (int kk = 0; kk < KS; kk++) {
        uint32_t a[4][4];
#pragma unroll
        for (int mi = 0; mi < 4; mi++) {
            int row = mrow0 + mi * 16 + arow_off;
            int ch  = 2 * kk + ach_off;
            uint32_t ad = aBase + row * SA + ((SWA ? (ch ^ (row & 7)) : ch) << 4);
            ldsm4(a[mi], ad);
        }
#pragma unroll
        for (int b = 0; b < NB; b++) {
            uint32_t bb = (b == 0) ? bBase0 : bBase1;
#pragma unroll
            for (int ni = 0; ni < 4; ni++) {
                int row = ncol0 + ni * 16 + brow_off;
                int ch  = 2 * kk + bch_off;
                uint32_t bd = bb + row * SB + ((SWB ? (ch ^ (row & 7)) : ch) << 4);
                uint32_t bf[4];
                ldsm4(bf, bd);
#pragma unroll
                for (int mi = 0; mi < 4; mi++) {
                    mma_f16(acc[mi][2 * ni],     a[mi], bf[0], bf[1]);
                    mma_f16(acc[mi][2 * ni + 1], a[mi], bf[2], bf[3]);
                }
            }
        }
    }
}

// Gate epilogue: acc (pre-activations, cols = unit*4+type) -> cell update ->
// h written hi/lo fp16 into swizzled smem tiles. Pair exchange via shfl.xor(1).
template<bool HASBIAS>
__device__ __forceinline__ void epilogue(float (&acc)[4][8][4], float (&cs)[4][8],
                                         char* sm, int hhOff, int hlOff,
                                         const float* bias,
                                         int mrow0, int ncol0, int lane)
{
    const int  odd   = lane & 1;
    const int  rb    = mrow0 + (lane >> 2) + (odd ? 8 : 0);
    const int  ub    = (ncol0 >> 2) + ((lane & 3) >> 1);
#pragma unroll
    for (int mi = 0; mi < 4; mi++) {
#pragma unroll
        for (int nj = 0; nj < 8; nj++) {
            float c0 = acc[mi][nj][0], c1 = acc[mi][nj][1];
            float c2 = acc[mi][nj][2], c3 = acc[mi][nj][3];
            if (HASBIAS) {
                int n0 = ncol0 + nj * 8 + 2 * (lane & 3);
                float b0 = bias[n0], b1 = bias[n0 + 1];
                c0 += b0; c1 += b1; c2 += b0; c3 += b1;
            }
            // even lanes hold (i,f) cols; odd lanes hold (g,o) cols; rows {r, r+8}
            float A0, A1, A2, A3;
            if (!odd) { A0 = sigf(c0);  A1 = sigf(c1); A2 = sigf(c2);  A3 = sigf(c3); }
            else      { A0 = tanh_(c0); A1 = sigf(c1); A2 = tanh_(c2); A3 = sigf(c3); }
            // exchange: even keeps row r (needs g,o from odd); odd keeps row r+8 (needs i,f)
            float v0 = odd ? A0 : A2;
            float v1 = odd ? A1 : A3;
            float r0 = __shfl_xor_sync(0xffffffffu, v0, 1);
            float r1 = __shfl_xor_sync(0xffffffffu, v1, 1);
            float iv = odd ? r0 : A0;
            float fv = odd ? r1 : A1;
            float gv = odd ? A2 : r0;
            float ov = odd ? A3 : r1;
            float cc = fv * cs[mi][nj] + iv * gv;
            cs[mi][nj] = cc;
            float hv = ov * tanh_(cc);
            int row = rb + mi * 16;
            int u   = ub + 2 * nj;
            __half hh = __float2half_rn(hv);
            __half hl = __float2half_rn(hv - __half2float(hh));
            int ch = u >> 3;
            int ba = row * 128 + ((ch ^ (row & 7)) << 4) + ((2 * u) & 15);
            *(__half*)(sm + hhOff + ba) = hh;
            *(__half*)(sm + hlOff + ba) = hl;
        }
    }
}

// split helper for weight fills
__device__ __forceinline__ void split2(float v, __half& hi, __half& lo) {
    hi = __float2half_rn(v);
    lo = __float2half_rn(v - __half2float(hi));
}

// =====================================================================
// Kernel 0: x -> h0 (hi/lo) -> global scratch
// =====================================================================
__global__ void __launch_bounds__(THREADS, 1) k_layer0(
    const float* __restrict__ x,
    const float* __restrict__ Wih, const float* __restrict__ Whh,
    const float* __restrict__ bih, const float* __restrict__ bhh)
{
    extern __shared__ __align__(1024) char sm[];
    const uint32_t sb = smem_u32(sm);
    const int tid = threadIdx.x, wid = tid >> 5, lane = tid & 31;
    const int mrow0 = (wid & 1) * 64;
    const int ncol0 = (wid >> 1) * 64;
    const int blk = blockIdx.x;

    // zero h tiles
    for (int i = tid; i < 32768 / 16; i += THREADS)
        ((uint4*)(sm + SM0_HH))[i] = make_uint4(0, 0, 0, 0);
    // zero Wih combined tile
    for (int i = tid; i < 28672 / 16; i += THREADS)
        ((uint4*)(sm + SM0_WIH))[i] = make_uint4(0, 0, 0, 0);
    __syncthreads();

    // Wih0 combined tile: cols 0-8 Whi, 9 bias_hi, 16-24 Wlo, 25 bias_lo, 32-40 Whi
    for (int idx = tid; idx < 256 * 9; idx += THREADS) {
        int g = idx / 9, i2 = idx - g * 9;
        int n = (g & 63) * 4 + (g >> 6);
        __half hi, lo; split2(Wih[idx], hi, lo);
        *(__half*)(sm + SM0_WIH + n * 112 + 2 * i2)        = hi;
        *(__half*)(sm + SM0_WIH + n * 112 + 2 * (16 + i2)) = lo;
        *(__half*)(sm + SM0_WIH + n * 112 + 2 * (32 + i2)) = hi;
    }
    for (int g = tid; g < 256; g += THREADS) {
        int n = (g & 63) * 4 + (g >> 6);
        __half hi, lo; split2(bih[g] + bhh[g], hi, lo);
        *(__half*)(sm + SM0_WIH + n * 112 + 18) = hi;   // col 9
        *(__half*)(sm + SM0_WIH + n * 112 + 50) = lo;   // col 25
    }
    // Whh0 hi/lo tiles (swizzled)
    for (int idx = tid; idx < 256 * 64; idx += THREADS) {
        int g = idx >> 6, k = idx & 63;
        int n = (g & 63) * 4 + (g >> 6);
        __half hi, lo; split2(Whh[idx], hi, lo);
        int ba = n * 128 + (((k >> 3) ^ (n & 7)) << 4) + ((2 * k) & 15);
        *(__half*)(sm + SM0_WHH_H + ba) = hi;
        *(__half*)(sm + SM0_WHH_L + ba) = lo;
    }
    __syncthreads();

    float cs[4][8];
#pragma unroll
    for (int a = 0; a < 4; a++)
#pragma unroll
        for (int b = 0; b < 8; b++) cs[a][b] = 0.f;

    for (int t = 0; t < T; t++) {
        // stage x_t: K=48 combined tile (xhi|1|0.., xhi|1|0.., xlo|0..)
        if (tid < MT) {
            const float* xr = x + ((size_t)(blk * MT + tid) * T + t) * 9;
            float v[9], vl[9];
#pragma unroll
            for (int i = 0; i < 9; i++) {
                v[i] = xr[i];
                __half h = __float2half_rn(v[i]);
                vl[i] = v[i] - __half2float(h);
            }
            char* rp = sm + SM0_X + tid * 112;
            uint4 c0 = make_uint4(f2h2(v[0], v[1]), f2h2(v[2], v[3]),
                                  f2h2(v[4], v[5]), f2h2(v[6], v[7]));
            uint4 c1 = make_uint4(f2h2(v[8], 1.0f), 0, 0, 0);
            uint4 c4 = make_uint4(f2h2(vl[0], vl[1]), f2h2(vl[2], vl[3]),
                                  f2h2(vl[4], vl[5]), f2h2(vl[6], vl[7]));
            uint4 c5 = make_uint4(f2h2(vl[8], 0.f), 0, 0, 0);
            ((uint4*)rp)[0] = c0;  ((uint4*)rp)[1] = c1;
            ((uint4*)rp)[2] = c0;  ((uint4*)rp)[3] = c1;
            ((uint4*)rp)[4] = c4;  ((uint4*)rp)[5] = c5;
        }
        __syncthreads();

        float acc[4][8][4];
#pragma unroll
        for (int a = 0; a < 4; a++)
#pragma unroll
            for (int b = 0; b < 8; b++)
#pragma unroll
                for (int q = 0; q < 4; q++) acc[a][b][q] = 0.f;

        gemm_acc<3, 112, 112, false, false, 1>(sb + SM0_X, sb + SM0_WIH, 0,
                                               acc, mrow0, ncol0, lane);
        gemm_acc<4, 128, 128, true, true, 2>(sb + SM0_HH, sb + SM0_WHH_H,
                                             sb + SM0_WHH_L, acc, mrow0, ncol0, lane);
        gemm_acc<4, 128, 128, true, true, 1>(sb + SM0_HL, sb + SM0_WHH_H, 0,
                                             acc, mrow0, ncol0, lane);
        __syncthreads();

        epilogue<false>(acc, cs, sm, SM0_HH, SM0_HL, nullptr, mrow0, ncol0, lane);
        __syncthreads();

        // coalesced copy h0 tiles -> global scratch
        for (int i = tid; i < 1024; i += THREADS) {
            int row = i >> 3, ch = i & 7;
            uint32_t sa = row * 128 + ((ch ^ (row & 7)) << 4);
            size_t gi = ((size_t)t * B + (size_t)blk * MT + row) * 8 + ch;
            g_h0hi[gi] = *(uint4*)(sm + SM0_HH + sa);
            g_h0lo[gi] = *(uint4*)(sm + SM0_HL + sa);
        }
    }
}

// =====================================================================
// Kernel 1: h0 -> LSTM -> LayerNorm(h_T) -> out
// =====================================================================
__global__ void __launch_bounds__(THREADS, 1) k_layer1(
    const float* __restrict__ Wih, const float* __restrict__ Whh,
    const float* __restrict__ bih, const float* __restrict__ bhh,
    const float* __restrict__ gamma, const float* __restrict__ beta,
    float* __restrict__ out)
{
    extern __shared__ __align__(1024) char sm[];
    const uint32_t sb = smem_u32(sm);
    const int tid = threadIdx.x, wid = tid >> 5, lane = tid & 31;
    const int mrow0 = (wid & 1) * 64;
    const int ncol0 = (wid >> 1) * 64;
    const int blk = blockIdx.x;

    // zero h1 tiles
    for (int i = tid; i < 32768 / 16; i += THREADS)
        ((uint4*)(sm + SM1_H1H))[i] = make_uint4(0, 0, 0, 0);
    // weights (swizzled hi/lo) + bias table (reordered)
    for (int idx = tid; idx < 256 * 64; idx += THREADS) {
        int g = idx >> 6, k = idx & 63;
        int n = (g & 63) * 4 + (g >> 6);
        int ba = n * 128 + (((k >> 3) ^ (n & 7)) << 4) + ((2 * k) & 15);
        __half hi, lo;
        split2(Wih[idx], hi, lo);
        *(__half*)(sm + SM1_WIH_H + ba) = hi;
        *(__half*)(sm + SM1_WIH_L + ba) = lo;
        split2(Whh[idx], hi, lo);
        *(__half*)(sm + SM1_WHH_H + ba) = hi;
        *(__half*)(sm + SM1_WHH_L + ba) = lo;
    }
    for (int g = tid; g < 256; g += THREADS) {
        int n = (g & 63) * 4 + (g >> 6);
        ((float*)(sm + SM1_BIAS))[n] = bih[g] + bhh[g];
    }
    __syncthreads();

    float cs[4][8];
#pragma unroll
    for (int a = 0; a < 4; a++)
#pragma unroll
        for (int b = 0; b < 8; b++) cs[a][b] = 0.f;

    for (int t = 0; t < T; t++) {
        // stage h0_t hi/lo from scratch (coalesced uint4)
        for (int i = tid; i < 1024; i += THREADS) {
            int row = i >> 3, ch = i & 7;
            size_t gi = ((size_t)t * B + (size_t)blk * MT + row) * 8 + ch;
            uint32_t sa = row * 128 + ((ch ^ (row & 7)) << 4);
            *(uint4*)(sm + SM1_XH + sa) = g_h0hi[gi];
            *(uint4*)(sm + SM1_XL + sa) = g_h0lo[gi];
        }
        __syncthreads();

        float acc[4][8][4];
#pragma unroll
        for (int a = 0; a < 4; a++)
#pragma unroll
            for (int b = 0; b < 8; b++)
#pragma unroll
                for (int q = 0; q < 4; q++) acc[a][b][q] = 0.f;

        gemm_acc<4, 128, 128, true, true, 2>(sb + SM1_XH, sb + SM1_WIH_H,
                                             sb + SM1_WIH_L, acc, mrow0, ncol0, lane);
        gemm_acc<4, 128, 128, true, true, 1>(sb + SM1_XL, sb + SM1_WIH_H, 0,
                                             acc, mrow0, ncol0, lane);
        gemm_acc<4, 128, 128, true, true, 2>(sb + SM1_H1H, sb + SM1_WHH_H,
                                             sb + SM1_WHH_L, acc, mrow0, ncol0, lane);
        gemm_acc<4, 128, 128, true, true, 1>(sb + SM1_H1L, sb + SM1_WHH_H, 0,
                                             acc, mrow0, ncol0, lane);
        __syncthreads();

        epilogue<true>(acc, cs, sm, SM1_H1H, SM1_H1L,
                       (const float*)(sm + SM1_BIAS), mrow0, ncol0, lane);
        __syncthreads();
    }

    // LayerNorm over final h1 (hi+lo reconstruct ~fp32), one thread per sample
    if (tid < MT) {
        int row = tid;
        float hv[64];
#pragma unroll
        for (int ch = 0; ch < 8; ch++) {
            uint32_t sa = row * 128 + ((ch ^ (row & 7)) << 4);
            uint4 vh = *(uint4*)(sm + SM1_H1H + sa);
            uint4 vl = *(uint4*)(sm + SM1_H1L + sa);
            const __half2* ph = (const __half2*)&vh;
            const __half2* pl = (const __half2*)&vl;
#pragma unroll
            for (int q = 0; q < 4; q++) {
                float2 a = __half22float2(ph[q]);
                float2 b2 = __half22float2(pl[q]);
                hv[ch * 8 + 2 * q]     = a.x + b2.x;
                hv[ch * 8 + 2 * q + 1] = a.y + b2.y;
            }
        }
        float s = 0.f;
#pragma unroll
        for (int k = 0; k < 64; k++) s += hv[k];
        float mean = s * (1.f / 64.f);
        float vs = 0.f;
#pragma unroll
        for (int k = 0; k < 64; k++) { float d = hv[k] - mean; vs += d * d; }
        float rstd = rsqrtf(vs * (1.f / 64.f) + 1e-5f);
        float4* op = (float4*)(out + (size_t)(blk * MT + row) * 64);
#pragma unroll
        for (int k = 0; k < 64; k += 4) {
            float4 o;
            o.x = (hv[k + 0] - mean) * rstd * gamma[k + 0] + beta[k + 0];
            o.y = (hv[k + 1] - mean) * rstd * gamma[k + 1] + beta[k + 1];
            o.z = (hv[k + 2] - mean) * rstd * gamma[k + 2] + beta[k + 2];
            o.w = (hv[k + 3] - mean) * rstd * gamma[k + 3] + beta[k + 3];
            op[k >> 2] = o;
        }
    }
}

// =====================================================================
extern "C" void kernel_launch(void* const* d_in, const int* in_sizes, int n_in,
                              void* d_out, int out_size) {
    (void)in_sizes; (void)n_in; (void)out_size;
    const float* x     = (const float*)d_in[0];
    const float* Wih0  = (const float*)d_in[1];
    const float* Whh0  = (const float*)d_in[2];
    const float* bih0  = (const float*)d_in[3];
    const float* bhh0  = (const float*)d_in[4];
    const float* Wih1  = (const float*)d_in[5];
    const float* Whh1  = (const float*)d_in[6];
    const float* bih1  = (const float*)d_in[7];
    const float* bhh1  = (const float*)d_in[8];
    const float* gamma = (const float*)d_in[9];
    const float* beta  = (const float*)d_in[10];
    float* out = (float*)d_out;

    cudaFuncSetAttribute(k_layer0, cudaFuncAttributeMaxDynamicSharedMemorySize, SM0_TOTAL);
    cudaFuncSetAttribute(k_layer1, cudaFuncAttributeMaxDynamicSharedMemorySize, SM1_TOTAL);

    k_layer0<<<B / MT, THREADS, SM0_TOTAL>>>(x, Wih0, Whh0, bih0, bhh0);
    k_layer1<<<B / MT, THREADS, SM1_TOTAL>>>(Wih1, Whh1, bih1, bhh1, gamma, beta, out);
}

// round 8
// speedup vs baseline: 3.2007x; 1.1028x over previous
#include <cuda_runtime.h>
#include <cuda_fp16.h>
#include <cstdint>
#include <cstddef>

constexpr int B  = 65536;
constexpr int T  = 30;
constexpr int MT = 128;          // samples per CTA
constexpr int THREADS = 512;     // 16 warps: 2 (m) x 8 (n), warp tile 64x32

// ---------------- Kernel0 smem offsets (bytes) ----------------
constexpr int SM0_X     = 0;       // [128 rows][stride 112B]  K=48 combined x tile
constexpr int SM0_WIH   = 14336;   // [256 n][stride 112B]     combined Wih0 hi/lo + bias
constexpr int SM0_HH    = 43008;   // [128][128B] swizzled     h0 hi
constexpr int SM0_HL    = 59392;   // h0 lo
constexpr int SM0_WHH_H = 75776;   // [256][128B] swizzled
constexpr int SM0_WHH_L = 108544;
constexpr int SM0_TOTAL = 141312;

// ---------------- Kernel1 smem offsets ----------------
constexpr int SM1_XH    = 0;       // staged h0 hi [128][128B] swz
constexpr int SM1_XL    = 16384;
constexpr int SM1_H1H   = 32768;   // h1 hi
constexpr int SM1_H1L   = 49152;
constexpr int SM1_WIH_H = 65536;   // [256][128B] swz
constexpr int SM1_WIH_L = 98304;
constexpr int SM1_WHH_H = 131072;
constexpr int SM1_WHH_L = 163840;
constexpr int SM1_BIAS  = 196608;  // 256 f32, indexed by reordered gate col
constexpr int SM1_TOTAL = 197632;

// scratch: layer0 h (hi/lo fp16), [t][sample][8 x 16B chunks], coalesced both ways
__device__ uint4 g_h0hi[(size_t)T * B * 8];
__device__ uint4 g_h0lo[(size_t)T * B * 8];

// ---------------- helpers ----------------
__device__ __forceinline__ uint32_t smem_u32(const void* p) {
    uint32_t a;
    asm("{ .reg .u64 t; cvta.to.shared.u64 t, %1; cvt.u32.u64 %0, t; }"
        : "=r"(a) : "l"(p));
    return a;
}
__device__ __forceinline__ float sigf(float x) {
    return __fdividef(1.f, 1.f + __expf(-x));
}
__device__ __forceinline__ float tanh_(float x) {
    return __fdividef(2.f, 1.f + __expf(-2.f * x)) - 1.f;
}
__device__ __forceinline__ uint32_t f2h2(float a, float b) {
    __half2 h = __floats2half2_rn(a, b);
    return *reinterpret_cast<uint32_t*>(&h);
}

__device__ __forceinline__ void ldsm4(uint32_t (&r)[4], uint32_t addr) {
    asm volatile("ldmatrix.sync.aligned.m8n8.x4.shared.b16 {%0,%1,%2,%3}, [%4];"
        : "=r"(r[0]), "=r"(r[1]), "=r"(r[2]), "=r"(r[3]) : "r"(addr));
}
__device__ __forceinline__ void mma_f16(float (&d)[4], const uint32_t (&a)[4],
                                        uint32_t b0, uint32_t b1) {
    asm volatile(
        "mma.sync.aligned.m16n8k16.row.col.f32.f16.f16.f32 "
        "{%0,%1,%2,%3},{%4,%5,%6,%7},{%8,%9},{%0,%1,%2,%3};"
        : "+f"(d[0]), "+f"(d[1]), "+f"(d[2]), "+f"(d[3])
        : "r"(a[0]), "r"(a[1]), "r"(a[2]), "r"(a[3]), "r"(b0), "r"(b1));
}

// Warp GEMM: A tile (64 rows) x NB B tiles (32 n-cols each), acc[4][4][4].
// KS k16-steps; strides in bytes; SW = XOR-16B-chunk swizzle for 128B-stride tiles.
template<int KS, int SA, int SB, bool SWA, bool SWB, int NB>
__device__ __forceinline__ void gemm_acc(uint32_t aBase, uint32_t bBase0, uint32_t bBase1,
                                         float (&acc)[4][4][4],
                                         int mrow0, int ncol0, int lane)
{
    const int grp = lane >> 3, j = lane & 7;
    const int arow_off = ((grp & 1) << 3) + j;
    const int ach_off  = grp >> 1;
    const int brow_off = ((grp >> 1) << 3) + j;
    const int bch_off  = grp & 1;
#pragma unroll
    for (int kk = 0; kk < KS; kk++) {
        uint32_t a[4][4];
#pragma unroll
        for (int mi = 0; mi < 4; mi++) {
            int row = mrow0 + mi * 16 + arow_off;
            int ch  = 2 * kk + ach_off;
            uint32_t ad = aBase + row * SA + ((SWA ? (ch ^ (row & 7)) : ch) << 4);
            ldsm4(a[mi], ad);
        }
#pragma unroll
        for (int b = 0; b < NB; b++) {
            uint32_t bb = (b == 0) ? bBase0 : bBase1;
#pragma unroll
            for (int ni = 0; ni < 2; ni++) {
                int row = ncol0 + ni * 16 + brow_off;
                int ch  = 2 * kk + bch_off;
                uint32_t bd = bb + row * SB + ((SWB ? (ch ^ (row & 7)) : ch) << 4);
                uint32_t bf[4];
                ldsm4(bf, bd);
#pragma unroll
                for (int mi = 0; mi < 4; mi++) {
                    mma_f16(acc[mi][2 * ni],     a[mi], bf[0], bf[1]);
                    mma_f16(acc[mi][2 * ni + 1], a[mi], bf[2], bf[3]);
                }
            }
        }
    }
}

// Gate epilogue: acc (pre-activations, cols = unit*4+type) -> cell update ->
// h written hi/lo fp16 into swizzled smem tiles. Pair exchange via shfl.xor(1).
template<bool HASBIAS>
__device__ __forceinline__ void epilogue(float (&acc)[4][4][4], float (&cs)[4][4],
                                         char* sm, int hhOff, int hlOff,
                                         const float* bias,
                                         int mrow0, int ncol0, int lane)
{
    const int  odd   = lane & 1;
    const int  rb    = mrow0 + (lane >> 2) + (odd ? 8 : 0);
    const int  ub    = (ncol0 >> 2) + ((lane & 3) >> 1);
#pragma unroll
    for (int mi = 0; mi < 4; mi++) {
#pragma unroll
        for (int nj = 0; nj < 4; nj++) {
            float c0 = acc[mi][nj][0], c1 = acc[mi][nj][1];
            float c2 = acc[mi][nj][2], c3 = acc[mi][nj][3];
            if (HASBIAS) {
                int n0 = ncol0 + nj * 8 + 2 * (lane & 3);
                float b0 = bias[n0], b1 = bias[n0 + 1];
                c0 += b0; c1 += b1; c2 += b0; c3 += b1;
            }
            // even lanes hold (i,f) cols; odd lanes hold (g,o) cols; rows {r, r+8}
            float A0, A1, A2, A3;
            if (!odd) { A0 = sigf(c0);  A1 = sigf(c1); A2 = sigf(c2);  A3 = sigf(c3); }
            else      { A0 = tanh_(c0); A1 = sigf(c1); A2 = tanh_(c2); A3 = sigf(c3); }
            // exchange: even keeps row r (needs g,o from odd); odd keeps row r+8 (needs i,f)
            float v0 = odd ? A0 : A2;
            float v1 = odd ? A1 : A3;
            float r0 = __shfl_xor_sync(0xffffffffu, v0, 1);
            float r1 = __shfl_xor_sync(0xffffffffu, v1, 1);
            float iv = odd ? r0 : A0;
            float fv = odd ? r1 : A1;
            float gv = odd ? A2 : r0;
            float ov = odd ? A3 : r1;
            float cc = fv * cs[mi][nj] + iv * gv;
            cs[mi][nj] = cc;
            float hv = ov * tanh_(cc);
            int row = rb + mi * 16;
            int u   = ub + 2 * nj;
            __half hh = __float2half_rn(hv);
            __half hl = __float2half_rn(hv - __half2float(hh));
            int ch = u >> 3;
            int ba = row * 128 + ((ch ^ (row & 7)) << 4) + ((2 * u) & 15);
            *(__half*)(sm + hhOff + ba) = hh;
            *(__half*)(sm + hlOff + ba) = hl;
        }
    }
}

// split helper for weight fills
__device__ __forceinline__ void split2(float v, __half& hi, __half& lo) {
    hi = __float2half_rn(v);
    lo = __float2half_rn(v - __half2float(hi));
}

// =====================================================================
// Kernel 0: x -> h0 (hi/lo) -> global scratch
// =====================================================================
__global__ void __launch_bounds__(THREADS, 1) k_layer0(
    const float* __restrict__ x,
    const float* __restrict__ Wih, const float* __restrict__ Whh,
    const float* __restrict__ bih, const float* __restrict__ bhh)
{
    extern __shared__ __align__(1024) char sm[];
    const uint32_t sb = smem_u32(sm);
    const int tid = threadIdx.x, wid = tid >> 5, lane = tid & 31;
    const int mrow0 = (wid & 1) * 64;
    const int ncol0 = (wid >> 1) * 32;
    const int blk = blockIdx.x;

    // zero h tiles + Wih combined tile
    for (int i = tid; i < 32768 / 16; i += THREADS)
        ((uint4*)(sm + SM0_HH))[i] = make_uint4(0, 0, 0, 0);
    for (int i = tid; i < 28672 / 16; i += THREADS)
        ((uint4*)(sm + SM0_WIH))[i] = make_uint4(0, 0, 0, 0);
    __syncthreads();

    // Wih0 combined tile: cols 0-8 Whi, 9 bias_hi, 16-24 Wlo, 25 bias_lo, 32-40 Whi
    for (int idx = tid; idx < 256 * 9; idx += THREADS) {
        int g = idx / 9, i2 = idx - g * 9;
        int n = (g & 63) * 4 + (g >> 6);
        __half hi, lo; split2(Wih[idx], hi, lo);
        *(__half*)(sm + SM0_WIH + n * 112 + 2 * i2)        = hi;
        *(__half*)(sm + SM0_WIH + n * 112 + 2 * (16 + i2)) = lo;
        *(__half*)(sm + SM0_WIH + n * 112 + 2 * (32 + i2)) = hi;
    }
    for (int g = tid; g < 256; g += THREADS) {
        int n = (g & 63) * 4 + (g >> 6);
        __half hi, lo; split2(bih[g] + bhh[g], hi, lo);
        *(__half*)(sm + SM0_WIH + n * 112 + 18) = hi;   // col 9
        *(__half*)(sm + SM0_WIH + n * 112 + 50) = lo;   // col 25
    }
    // Whh0 hi/lo tiles (swizzled)
    for (int idx = tid; idx < 256 * 64; idx += THREADS) {
        int g = idx >> 6, k = idx & 63;
        int n = (g & 63) * 4 + (g >> 6);
        __half hi, lo; split2(Whh[idx], hi, lo);
        int ba = n * 128 + (((k >> 3) ^ (n & 7)) << 4) + ((2 * k) & 15);
        *(__half*)(sm + SM0_WHH_H + ba) = hi;
        *(__half*)(sm + SM0_WHH_L + ba) = lo;
    }
    __syncthreads();

    float cs[4][4];
#pragma unroll
    for (int a = 0; a < 4; a++)
#pragma unroll
        for (int b = 0; b < 4; b++) cs[a][b] = 0.f;

    // prefetch x for t=0
    float xv[9];
    if (tid < MT) {
        const float* xr = x + ((size_t)(blk * MT + tid) * T + 0) * 9;
#pragma unroll
        for (int i = 0; i < 9; i++) xv[i] = xr[i];
    }

    for (int t = 0; t < T; t++) {
        // stage x_t: K=48 combined tile (xhi|1|0.., xhi|1|0.., xlo|0..)
        if (tid < MT) {
            float vl[9];
#pragma unroll
            for (int i = 0; i < 9; i++) {
                __half h = __float2half_rn(xv[i]);
                vl[i] = xv[i] - __half2float(h);
            }
            char* rp = sm + SM0_X + tid * 112;
            uint4 c0 = make_uint4(f2h2(xv[0], xv[1]), f2h2(xv[2], xv[3]),
                                  f2h2(xv[4], xv[5]), f2h2(xv[6], xv[7]));
            uint4 c1 = make_uint4(f2h2(xv[8], 1.0f), 0, 0, 0);
            uint4 c4 = make_uint4(f2h2(vl[0], vl[1]), f2h2(vl[2], vl[3]),
                                  f2h2(vl[4], vl[5]), f2h2(vl[6], vl[7]));
            uint4 c5 = make_uint4(f2h2(vl[8], 0.f), 0, 0, 0);
            ((uint4*)rp)[0] = c0;  ((uint4*)rp)[1] = c1;
            ((uint4*)rp)[2] = c0;  ((uint4*)rp)[3] = c1;
            ((uint4*)rp)[4] = c4;  ((uint4*)rp)[5] = c5;
        }
        __syncthreads();

        // prefetch x for t+1 (overlaps with GEMM below)
        if (t + 1 < T && tid < MT) {
            const float* xr = x + ((size_t)(blk * MT + tid) * T + (t + 1)) * 9;
#pragma unroll
            for (int i = 0; i < 9; i++) xv[i] = xr[i];
        }

        float acc[4][4][4];
#pragma unroll
        for (int a = 0; a < 4; a++)
#pragma unroll
            for (int b = 0; b < 4; b++)
#pragma unroll
                for (int q = 0; q < 4; q++) acc[a][b][q] = 0.f;

        gemm_acc<3, 112, 112, false, false, 1>(sb + SM0_X, sb + SM0_WIH, 0,
                                               acc, mrow0, ncol0, lane);
        gemm_acc<4, 128, 128, true, true, 2>(sb + SM0_HH, sb + SM0_WHH_H,
                                             sb + SM0_WHH_L, acc, mrow0, ncol0, lane);
        gemm_acc<4, 128, 128, true, true, 1>(sb + SM0_HL, sb + SM0_WHH_H, 0,
                                             acc, mrow0, ncol0, lane);
        __syncthreads();

        epilogue<false>(acc, cs, sm, SM0_HH, SM0_HL, nullptr, mrow0, ncol0, lane);
        __syncthreads();

        // coalesced copy h0 tiles -> global scratch (read-only vs next GEMM; the
        // next gemm-sync orders it before epilogue t+1 overwrites the tiles)
        for (int i = tid; i < 1024; i += THREADS) {
            int row = i >> 3, ch = i & 7;
            uint32_t sa = row * 128 + ((ch ^ (row & 7)) << 4);
            size_t gi = ((size_t)t * B + (size_t)blk * MT + row) * 8 + ch;
            g_h0hi[gi] = *(uint4*)(sm + SM0_HH + sa);
            g_h0lo[gi] = *(uint4*)(sm + SM0_HL + sa);
        }
    }
}

// =====================================================================
// Kernel 1: h0 -> LSTM -> LayerNorm(h_T) -> out
// =====================================================================
__global__ void __launch_bounds__(THREADS, 1) k_layer1(
    const float* __restrict__ Wih, const float* __restrict__ Whh,
    const float* __restrict__ bih, const float* __restrict__ bhh,
    const float* __restrict__ gamma, const float* __restrict__ beta,
    float* __restrict__ out)
{
    extern __shared__ __align__(1024) char sm[];
    const uint32_t sb = smem_u32(sm);
    const int tid = threadIdx.x, wid = tid >> 5, lane = tid & 31;
    const int mrow0 = (wid & 1) * 64;
    const int ncol0 = (wid >> 1) * 32;
    const int blk = blockIdx.x;

    // zero h1 tiles
    for (int i = tid; i < 32768 / 16; i += THREADS)
        ((uint4*)(sm + SM1_H1H))[i] = make_uint4(0, 0, 0, 0);
    // weights (swizzled hi/lo) + bias table (reordered)
    for (int idx = tid; idx < 256 * 64; idx += THREADS) {
        int g = idx >> 6, k = idx & 63;
        int n = (g & 63) * 4 + (g >> 6);
        int ba = n * 128 + (((k >> 3) ^ (n & 7)) << 4) + ((2 * k) & 15);
        __half hi, lo;
        split2(Wih[idx], hi, lo);
        *(__half*)(sm + SM1_WIH_H + ba) = hi;
        *(__half*)(sm + SM1_WIH_L + ba) = lo;
        split2(Whh[idx], hi, lo);
        *(__half*)(sm + SM1_WHH_H + ba) = hi;
        *(__half*)(sm + SM1_WHH_L + ba) = lo;
    }
    for (int g = tid; g < 256; g += THREADS) {
        int n = (g & 63) * 4 + (g >> 6);
        ((float*)(sm + SM1_BIAS))[n] = bih[g] + bhh[g];
    }
    __syncthreads();

    float cs[4][4];
#pragma unroll
    for (int a = 0; a < 4; a++)
#pragma unroll
        for (int b = 0; b < 4; b++) cs[a][b] = 0.f;

    // prefetch h0 for t=0 (1024 uint4 pairs, 2 per thread; layout is linear in i)
    uint4 ph[2], pl[2];
    {
        size_t base = ((size_t)0 * B + (size_t)blk * MT) * 8;
#pragma unroll
        for (int r = 0; r < 2; r++) {
            ph[r] = g_h0hi[base + tid + r * THREADS];
            pl[r] = g_h0lo[base + tid + r * THREADS];
        }
    }

    for (int t = 0; t < T; t++) {
        // stage h0_t from prefetched regs into swizzled X tiles
#pragma unroll
        for (int r = 0; r < 2; r++) {
            int i = tid + r * THREADS;
            int row = i >> 3, ch = i & 7;
            uint32_t sa = row * 128 + ((ch ^ (row & 7)) << 4);
            *(uint4*)(sm + SM1_XH + sa) = ph[r];
            *(uint4*)(sm + SM1_XL + sa) = pl[r];
        }
        __syncthreads();

        // prefetch next timestep (overlaps with GEMM)
        if (t + 1 < T) {
            size_t base = ((size_t)(t + 1) * B + (size_t)blk * MT) * 8;
#pragma unroll
            for (int r = 0; r < 2; r++) {
                ph[r] = g_h0hi[base + tid + r * THREADS];
                pl[r] = g_h0lo[base + tid + r * THREADS];
            }
        }

        float acc[4][4][4];
#pragma unroll
        for (int a = 0; a < 4; a++)
#pragma unroll
            for (int b = 0; b < 4; b++)
#pragma unroll
                for (int q = 0; q < 4; q++) acc[a][b][q] = 0.f;

        gemm_acc<4, 128, 128, true, true, 2>(sb + SM1_XH, sb + SM1_WIH_H,
                                             sb + SM1_WIH_L, acc, mrow0, ncol0, lane);
        gemm_acc<4, 128, 128, true, true, 1>(sb + SM1_XL, sb + SM1_WIH_H, 0,
                                             acc, mrow0, ncol0, lane);
        gemm_acc<4, 128, 128, true, true, 2>(sb + SM1_H1H, sb + SM1_WHH_H,
                                             sb + SM1_WHH_L, acc, mrow0, ncol0, lane);
        gemm_acc<4, 128, 128, true, true, 1>(sb + SM1_H1L, sb + SM1_WHH_H, 0,
                                             acc, mrow0, ncol0, lane);
        __syncthreads();

        epilogue<true>(acc, cs, sm, SM1_H1H, SM1_H1L,
                       (const float*)(sm + SM1_BIAS), mrow0, ncol0, lane);
        __syncthreads();
    }

    // LayerNorm over final h1 (hi+lo reconstruct ~fp32), one thread per sample
    if (tid < MT) {
        int row = tid;
        float hv[64];
#pragma unroll
        for (int ch = 0; ch < 8; ch++) {
            uint32_t sa = row * 128 + ((ch ^ (row & 7)) << 4);
            uint4 vh = *(uint4*)(sm + SM1_H1H + sa);
            uint4 vl = *(uint4*)(sm + SM1_H1L + sa);
            const __half2* phh = (const __half2*)&vh;
            const __half2* pll = (const __half2*)&vl;
#pragma unroll
            for (int q = 0; q < 4; q++) {
                float2 a = __half22float2(phh[q]);
                float2 b2 = __half22float2(pll[q]);
                hv[ch * 8 + 2 * q]     = a.x + b2.x;
                hv[ch * 8 + 2 * q + 1] = a.y + b2.y;
            }
        }
        float s = 0.f;
#pragma unroll
        for (int k = 0; k < 64; k++) s += hv[k];
        float mean = s * (1.f / 64.f);
        float vs = 0.f;
#pragma unroll
        for (int k = 0; k < 64; k++) { float d = hv[k] - mean; vs += d * d; }
        float rstd = rsqrtf(vs * (1.f / 64.f) + 1e-5f);
        float4* op = (float4*)(out + (size_t)(blk * MT + row) * 64);
#pragma unroll
        for (int k = 0; k < 64; k += 4) {
            float4 o;
            o.x = (hv[k + 0] - mean) * rstd * gamma[k + 0] + beta[k + 0];
            o.y = (hv[k + 1] - mean) * rstd * gamma[k + 1] + beta[k + 1];
            o.z = (hv[k + 2] - mean) * rstd * gamma[k + 2] + beta[k + 2];
            o.w = (hv[k + 3] - mean) * rstd * gamma[k + 3] + beta[k + 3];
            op[k >> 2] = o;
        }
    }
}

// =====================================================================
extern "C" void kernel_launch(void* const* d_in, const int* in_sizes, int n_in,
                              void* d_out, int out_size) {
    (void)in_sizes; (void)n_in; (void)out_size;
    const float* x     = (const float*)d_in[0];
    const float* Wih0  = (const float*)d_in[1];
    const float* Whh0  = (const float*)d_in[2];
    const float* bih0  = (const float*)d_in[3];
    const float* bhh0  = (const float*)d_in[4];
    const float* Wih1  = (const float*)d_in[5];
    const float* Whh1  = (const float*)d_in[6];
    const float* bih1  = (const float*)d_in[7];
    const float* bhh1  = (const float*)d_in[8];
    const float* gamma = (const float*)d_in[9];
    const float* beta  = (const float*)d_in[10];
    float* out = (float*)d_out;

    cudaFuncSetAttribute(k_layer0, cudaFuncAttributeMaxDynamicSharedMemorySize, SM0_TOTAL);
    cudaFuncSetAttribute(k_layer1, cudaFuncAttributeMaxDynamicSharedMemorySize, SM1_TOTAL);

    k_layer0<<<B / MT, THREADS, SM0_TOTAL>>>(x, Wih0, Whh0, bih0, bhh0);
    k_layer1<<<B / MT, THREADS, SM1_TOTAL>>>(Wih1, Whh1, bih1, bhh1, gamma, beta, out);
}

// round 9
// speedup vs baseline: 3.2502x; 1.0154x over previous
#include <cuda_runtime.h>
#include <cuda_fp16.h>
#include <cstdint>
#include <cstddef>

constexpr int B  = 65536;
constexpr int T  = 30;
constexpr int MT = 128;          // samples per CTA
constexpr int THREADS = 512;     // 16 warps: 2 (m) x 8 (n), warp tile 64x32

// ---------------- Kernel0 smem offsets (bytes) ----------------
constexpr int SM0_X     = 0;       // [128 rows][stride 112B]  K=48 combined x tile
constexpr int SM0_WIH   = 14336;   // [256 n][stride 112B]     combined Wih0 hi/lo + bias
constexpr int SM0_HH0   = 43008;   // h0 hi, ping  [128][128B] swz
constexpr int SM0_HH1   = 59392;   // h0 hi, pong
constexpr int SM0_HL0   = 75776;   // h0 lo, ping
constexpr int SM0_HL1   = 92160;   // h0 lo, pong
constexpr int SM0_WHH_H = 108544;  // [256][128B] swz
constexpr int SM0_WHH_L = 141312;
constexpr int SM0_TOTAL = 174080;

// ---------------- Kernel1 smem offsets ----------------
constexpr int SM1_XH    = 0;       // staged h0 hi [128][128B] swz
constexpr int SM1_XL    = 16384;
constexpr int SM1_H1H0  = 32768;   // h1 hi ping
constexpr int SM1_H1H1  = 49152;   // h1 hi pong
constexpr int SM1_H1L0  = 65536;   // h1 lo ping
constexpr int SM1_H1L1  = 81920;   // h1 lo pong
constexpr int SM1_WIH_H = 98304;   // [256][128B] swz
constexpr int SM1_WIH_L = 131072;
constexpr int SM1_WHH_H = 163840;
constexpr int SM1_WHH_L = 196608;
constexpr int SM1_BIAS  = 229376;  // 256 f32, indexed by reordered gate col
constexpr int SM1_TOTAL = 230400;

// scratch: layer0 h (hi/lo fp16), [t][sample][8 x 16B chunks], coalesced both ways
__device__ uint4 g_h0hi[(size_t)T * B * 8];
__device__ uint4 g_h0lo[(size_t)T * B * 8];

// ---------------- helpers ----------------
__device__ __forceinline__ uint32_t smem_u32(const void* p) {
    uint32_t a;
    asm("{ .reg .u64 t; cvta.to.shared.u64 t, %1; cvt.u32.u64 %0, t; }"
        : "=r"(a) : "l"(p));
    return a;
}
__device__ __forceinline__ float sigf(float x) {
    return __fdividef(1.f, 1.f + __expf(-x));
}
__device__ __forceinline__ float tanh_(float x) {
    return __fdividef(2.f, 1.f + __expf(-2.f * x)) - 1.f;
}
__device__ __forceinline__ uint32_t f2h2(float a, float b) {
    __half2 h = __floats2half2_rn(a, b);
    return *reinterpret_cast<uint32_t*>(&h);
}

__device__ __forceinline__ void ldsm4(uint32_t (&r)[4], uint32_t addr) {
    asm volatile("ldmatrix.sync.aligned.m8n8.x4.shared.b16 {%0,%1,%2,%3}, [%4];"
        : "=r"(r[0]), "=r"(r[1]), "=r"(r[2]), "=r"(r[3]) : "r"(addr));
}
__device__ __forceinline__ void mma_f16(float (&d)[4], const uint32_t (&a)[4],
                                        uint32_t b0, uint32_t b1) {
    asm volatile(
        "mma.sync.aligned.m16n8k16.row.col.f32.f16.f16.f32 "
        "{%0,%1,%2,%3},{%4,%5,%6,%7},{%8,%9},{%0,%1,%2,%3};"
        : "+f"(d[0]), "+f"(d[1]), "+f"(d[2]), "+f"(d[3])
        : "r"(a[0]), "r"(a[1]), "r"(a[2]), "r"(a[3]), "r"(b0), "r"(b1));
}

// Warp GEMM: A tile (64 rows) x NB B tiles (32 n-cols each), acc[4][4][4].
// KS k16-steps; strides in bytes; SW = XOR-16B-chunk swizzle for 128B-stride tiles.
template<int KS, int SA, int SB, bool SWA, bool SWB, int NB>
__device__ __forceinline__ void gemm_acc(uint32_t aBase, uint32_t bBase0, uint32_t bBase1,
                                         float (&acc)[4][4][4],
                                         int mrow0, int ncol0, int lane)
{
    const int grp = lane >> 3, j = lane & 7;
    const int arow_off = ((grp & 1) << 3) + j;
    const int ach_off  = grp >> 1;
    const int brow_off = ((grp >> 1) << 3) + j;
    const int bch_off  = grp & 1;
#pragma unroll
    for (int kk = 0; kk < KS; kk++) {
        uint32_t a[4][4];
#pragma unroll
        for (int mi = 0; mi < 4; mi++) {
            int row = mrow0 + mi * 16 + arow_off;
            int ch  = 2 * kk + ach_off;
            uint32_t ad = aBase + row * SA + ((SWA ? (ch ^ (row & 7)) : ch) << 4);
            ldsm4(a[mi], ad);
        }
#pragma unroll
        for (int b = 0; b < NB; b++) {
            uint32_t bb = (b == 0) ? bBase0 : bBase1;
#pragma unroll
            for (int ni = 0; ni < 2; ni++) {
                int row = ncol0 + ni * 16 + brow_off;
                int ch  = 2 * kk + bch_off;
                uint32_t bd = bb + row * SB + ((SWB ? (ch ^ (row & 7)) : ch) << 4);
                uint32_t bf[4];
                ldsm4(bf, bd);
#pragma unroll
                for (int mi = 0; mi < 4; mi++) {
                    mma_f16(acc[mi][2 * ni],     a[mi], bf[0], bf[1]);
                    mma_f16(acc[mi][2 * ni + 1], a[mi], bf[2], bf[3]);
                }
            }
        }
    }
}

// Gate epilogue: acc (pre-activations, cols = unit*4+type) -> cell update ->
// h written hi/lo fp16 into the DESTINATION (ping-pong) swizzled smem tiles.
// No barrier needed between GEMM and this: destination != GEMM source buffer.
template<bool HASBIAS>
__device__ __forceinline__ void epilogue(float (&acc)[4][4][4], float (&cs)[4][4],
                                         char* sm, int hhOff, int hlOff,
                                         const float* bias,
                                         int mrow0, int ncol0, int lane)
{
    const int  odd   = lane & 1;
    const int  rb    = mrow0 + (lane >> 2) + (odd ? 8 : 0);
    const int  ub    = (ncol0 >> 2) + ((lane & 3) >> 1);
#pragma unroll
    for (int mi = 0; mi < 4; mi++) {
#pragma unroll
        for (int nj = 0; nj < 4; nj++) {
            float c0 = acc[mi][nj][0], c1 = acc[mi][nj][1];
            float c2 = acc[mi][nj][2], c3 = acc[mi][nj][3];
            if (HASBIAS) {
                int n0 = ncol0 + nj * 8 + 2 * (lane & 3);
                float b0 = bias[n0], b1 = bias[n0 + 1];
                c0 += b0; c1 += b1; c2 += b0; c3 += b1;
            }
            // even lanes hold (i,f) cols; odd lanes hold (g,o) cols; rows {r, r+8}
            float A0, A1, A2, A3;
            if (!odd) { A0 = sigf(c0);  A1 = sigf(c1); A2 = sigf(c2);  A3 = sigf(c3); }
            else      { A0 = tanh_(c0); A1 = sigf(c1); A2 = tanh_(c2); A3 = sigf(c3); }
            // exchange: even keeps row r (needs g,o from odd); odd keeps row r+8 (needs i,f)
            float v0 = odd ? A0 : A2;
            float v1 = odd ? A1 : A3;
            float r0 = __shfl_xor_sync(0xffffffffu, v0, 1);
            float r1 = __shfl_xor_sync(0xffffffffu, v1, 1);
            float iv = odd ? r0 : A0;
            float fv = odd ? r1 : A1;
            float gv = odd ? A2 : r0;
            float ov = odd ? A3 : r1;
            float cc = fv * cs[mi][nj] + iv * gv;
            cs[mi][nj] = cc;
            float hv = ov * tanh_(cc);
            int row = rb + mi * 16;
            int u   = ub + 2 * nj;
            __half hh = __float2half_rn(hv);
            __half hl = __float2half_rn(hv - __half2float(hh));
            int ch = u >> 3;
            int ba = row * 128 + ((ch ^ (row & 7)) << 4) + ((2 * u) & 15);
            *(__half*)(sm + hhOff + ba) = hh;
            *(__half*)(sm + hlOff + ba) = hl;
        }
    }
}

// split helper for weight fills
__device__ __forceinline__ void split2(float v, __half& hi, __half& lo) {
    hi = __float2half_rn(v);
    lo = __float2half_rn(v - __half2float(hi));
}

// =====================================================================
// Kernel 0: x -> h0 (hi/lo) -> global scratch
// =====================================================================
__global__ void __launch_bounds__(THREADS, 1) k_layer0(
    const float* __restrict__ x,
    const float* __restrict__ Wih, const float* __restrict__ Whh,
    const float* __restrict__ bih, const float* __restrict__ bhh)
{
    extern __shared__ __align__(1024) char sm[];
    const uint32_t sb = smem_u32(sm);
    const int tid = threadIdx.x, wid = tid >> 5, lane = tid & 31;
    const int mrow0 = (wid & 1) * 64;
    const int ncol0 = (wid >> 1) * 32;
    const int blk = blockIdx.x;

    // zero both h buffer pairs + Wih combined tile
    for (int i = tid; i < 65536 / 16; i += THREADS)
        ((uint4*)(sm + SM0_HH0))[i] = make_uint4(0, 0, 0, 0);
    for (int i = tid; i < 28672 / 16; i += THREADS)
        ((uint4*)(sm + SM0_WIH))[i] = make_uint4(0, 0, 0, 0);
    __syncthreads();

    // Wih0 combined tile: cols 0-8 Whi, 9 bias_hi, 16-24 Wlo, 25 bias_lo, 32-40 Whi
    for (int idx = tid; idx < 256 * 9; idx += THREADS) {
        int g = idx / 9, i2 = idx - g * 9;
        int n = (g & 63) * 4 + (g >> 6);
        __half hi, lo; split2(Wih[idx], hi, lo);
        *(__half*)(sm + SM0_WIH + n * 112 + 2 * i2)        = hi;
        *(__half*)(sm + SM0_WIH + n * 112 + 2 * (16 + i2)) = lo;
        *(__half*)(sm + SM0_WIH + n * 112 + 2 * (32 + i2)) = hi;
    }
    for (int g = tid; g < 256; g += THREADS) {
        int n = (g & 63) * 4 + (g >> 6);
        __half hi, lo; split2(bih[g] + bhh[g], hi, lo);
        *(__half*)(sm + SM0_WIH + n * 112 + 18) = hi;   // col 9
        *(__half*)(sm + SM0_WIH + n * 112 + 50) = lo;   // col 25
    }
    // Whh0 hi/lo tiles (swizzled)
    for (int idx = tid; idx < 256 * 64; idx += THREADS) {
        int g = idx >> 6, k = idx & 63;
        int n = (g & 63) * 4 + (g >> 6);
        __half hi, lo; split2(Whh[idx], hi, lo);
        int ba = n * 128 + (((k >> 3) ^ (n & 7)) << 4) + ((2 * k) & 15);
        *(__half*)(sm + SM0_WHH_H + ba) = hi;
        *(__half*)(sm + SM0_WHH_L + ba) = lo;
    }
    __syncthreads();

    float cs[4][4];
#pragma unroll
    for (int a = 0; a < 4; a++)
#pragma unroll
        for (int b = 0; b < 4; b++) cs[a][b] = 0.f;

    // prefetch x for t=0
    float xv[9];
    if (tid < MT) {
        const float* xr = x + ((size_t)(blk * MT + tid) * T + 0) * 9;
#pragma unroll
        for (int i = 0; i < 9; i++) xv[i] = xr[i];
    }

    for (int t = 0; t < T; t++) {
        const int rdH = (t & 1) ? SM0_HH1 : SM0_HH0;
        const int rdL = (t & 1) ? SM0_HL1 : SM0_HL0;
        const int wrH = (t & 1) ? SM0_HH0 : SM0_HH1;
        const int wrL = (t & 1) ? SM0_HL0 : SM0_HL1;

        // store h_{t-1} -> global scratch (reads rd buffers: read/read vs GEMM)
        if (t > 0) {
            for (int i = tid; i < 1024; i += THREADS) {
                int row = i >> 3, ch = i & 7;
                uint32_t sa = row * 128 + ((ch ^ (row & 7)) << 4);
                size_t gi = ((size_t)(t - 1) * B + (size_t)blk * MT + row) * 8 + ch;
                g_h0hi[gi] = *(uint4*)(sm + rdH + sa);
                g_h0lo[gi] = *(uint4*)(sm + rdL + sa);
            }
        }

        // stage x_t: K=48 combined tile (xhi|1|0.., xhi|1|0.., xlo|0..)
        if (tid < MT) {
            float vl[9];
#pragma unroll
            for (int i = 0; i < 9; i++) {
                __half h = __float2half_rn(xv[i]);
                vl[i] = xv[i] - __half2float(h);
            }
            char* rp = sm + SM0_X + tid * 112;
            uint4 c0 = make_uint4(f2h2(xv[0], xv[1]), f2h2(xv[2], xv[3]),
                                  f2h2(xv[4], xv[5]), f2h2(xv[6], xv[7]));
            uint4 c1 = make_uint4(f2h2(xv[8], 1.0f), 0, 0, 0);
            uint4 c4 = make_uint4(f2h2(vl[0], vl[1]), f2h2(vl[2], vl[3]),
                                  f2h2(vl[4], vl[5]), f2h2(vl[6], vl[7]));
            uint4 c5 = make_uint4(f2h2(vl[8], 0.f), 0, 0, 0);
            ((uint4*)rp)[0] = c0;  ((uint4*)rp)[1] = c1;
            ((uint4*)rp)[2] = c0;  ((uint4*)rp)[3] = c1;
            ((uint4*)rp)[4] = c4;  ((uint4*)rp)[5] = c5;
        }
        __syncthreads();

        // prefetch x for t+1 (overlaps with GEMM below)
        if (t + 1 < T && tid < MT) {
            const float* xr = x + ((size_t)(blk * MT + tid) * T + (t + 1)) * 9;
#pragma unroll
            for (int i = 0; i < 9; i++) xv[i] = xr[i];
        }

        float acc[4][4][4];
#pragma unroll
        for (int a = 0; a < 4; a++)
#pragma unroll
            for (int b = 0; b < 4; b++)
#pragma unroll
                for (int q = 0; q < 4; q++) acc[a][b][q] = 0.f;

        gemm_acc<3, 112, 112, false, false, 1>(sb + SM0_X, sb + SM0_WIH, 0,
                                               acc, mrow0, ncol0, lane);
        gemm_acc<4, 128, 128, true, true, 2>(sb + rdH, sb + SM0_WHH_H,
                                             sb + SM0_WHH_L, acc, mrow0, ncol0, lane);
        gemm_acc<4, 128, 128, true, true, 1>(sb + rdL, sb + SM0_WHH_H, 0,
                                             acc, mrow0, ncol0, lane);

        // NO sync: epilogue writes ping-pong destination, disjoint from rd buffers
        epilogue<false>(acc, cs, sm, wrH, wrL, nullptr, mrow0, ncol0, lane);
        __syncthreads();
    }

    // store final h_{T-1} (lives in buf[T&1] = buf0)
    {
        const int rdH = (T & 1) ? SM0_HH1 : SM0_HH0;
        const int rdL = (T & 1) ? SM0_HL1 : SM0_HL0;
        for (int i = tid; i < 1024; i += THREADS) {
            int row = i >> 3, ch = i & 7;
            uint32_t sa = row * 128 + ((ch ^ (row & 7)) << 4);
            size_t gi = ((size_t)(T - 1) * B + (size_t)blk * MT + row) * 8 + ch;
            g_h0hi[gi] = *(uint4*)(sm + rdH + sa);
            g_h0lo[gi] = *(uint4*)(sm + rdL + sa);
        }
    }
}

// =====================================================================
// Kernel 1: h0 -> LSTM -> LayerNorm(h_T) -> out
// =====================================================================
__global__ void __launch_bounds__(THREADS, 1) k_layer1(
    const float* __restrict__ Wih, const float* __restrict__ Whh,
    const float* __restrict__ bih, const float* __restrict__ bhh,
    const float* __restrict__ gamma, const float* __restrict__ beta,
    float* __restrict__ out)
{
    extern __shared__ __align__(1024) char sm[];
    const uint32_t sb = smem_u32(sm);
    const int tid = threadIdx.x, wid = tid >> 5, lane = tid & 31;
    const int mrow0 = (wid & 1) * 64;
    const int ncol0 = (wid >> 1) * 32;
    const int blk = blockIdx.x;

    // zero both h1 buffer pairs
    for (int i = tid; i < 65536 / 16; i += THREADS)
        ((uint4*)(sm + SM1_H1H0))[i] = make_uint4(0, 0, 0, 0);
    // weights (swizzled hi/lo) + bias table (reordered)
    for (int idx = tid; idx < 256 * 64; idx += THREADS) {
        int g = idx >> 6, k = idx & 63;
        int n = (g & 63) * 4 + (g >> 6);
        int ba = n * 128 + (((k >> 3) ^ (n & 7)) << 4) + ((2 * k) & 15);
        __half hi, lo;
        split2(Wih[idx], hi, lo);
        *(__half*)(sm + SM1_WIH_H + ba) = hi;
        *(__half*)(sm + SM1_WIH_L + ba) = lo;
        split2(Whh[idx], hi, lo);
        *(__half*)(sm + SM1_WHH_H + ba) = hi;
        *(__half*)(sm + SM1_WHH_L + ba) = lo;
    }
    for (int g = tid; g < 256; g += THREADS) {
        int n = (g & 63) * 4 + (g >> 6);
        ((float*)(sm + SM1_BIAS))[n] = bih[g] + bhh[g];
    }
    __syncthreads();

    float cs[4][4];
#pragma unroll
    for (int a = 0; a < 4; a++)
#pragma unroll
        for (int b = 0; b < 4; b++) cs[a][b] = 0.f;

    // prefetch h0 for t=0 (2048 uint4 pairs, 2 per thread; layout linear in i)
    uint4 ph[2], pl[2];
    {
        size_t base = ((size_t)0 * B + (size_t)blk * MT) * 8;
#pragma unroll
        for (int r = 0; r < 2; r++) {
            ph[r] = g_h0hi[base + tid + r * THREADS];
            pl[r] = g_h0lo[base + tid + r * THREADS];
        }
    }

    for (int t = 0; t < T; t++) {
        const int rdH = (t & 1) ? SM1_H1H1 : SM1_H1H0;
        const int rdL = (t & 1) ? SM1_H1L1 : SM1_H1L0;
        const int wrH = (t & 1) ? SM1_H1H0 : SM1_H1H1;
        const int wrL = (t & 1) ? SM1_H1L0 : SM1_H1L1;

        // stage h0_t from prefetched regs into swizzled X tiles
#pragma unroll
        for (int r = 0; r < 2; r++) {
            int i = tid + r * THREADS;
            int row = i >> 3, ch = i & 7;
            uint32_t sa = row * 128 + ((ch ^ (row & 7)) << 4);
            *(uint4*)(sm + SM1_XH + sa) = ph[r];
            *(uint4*)(sm + SM1_XL + sa) = pl[r];
        }
        __syncthreads();

        // prefetch next timestep (overlaps with GEMM)
        if (t + 1 < T) {
            size_t base = ((size_t)(t + 1) * B + (size_t)blk * MT) * 8;
#pragma unroll
            for (int r = 0; r < 2; r++) {
                ph[r] = g_h0hi[base + tid + r * THREADS];
                pl[r] = g_h0lo[base + tid + r * THREADS];
            }
        }

        float acc[4][4][4];
#pragma unroll
        for (int a = 0; a < 4; a++)
#pragma unroll
            for (int b = 0; b < 4; b++)
#pragma unroll
                for (int q = 0; q < 4; q++) acc[a][b][q] = 0.f;

        gemm_acc<4, 128, 128, true, true, 2>(sb + SM1_XH, sb + SM1_WIH_H,
                                             sb + SM1_WIH_L, acc, mrow0, ncol0, lane);
        gemm_acc<4, 128, 128, true, true, 1>(sb + SM1_XL, sb + SM1_WIH_H, 0,
                                             acc, mrow0, ncol0, lane);
        gemm_acc<4, 128, 128, true, true, 2>(sb + rdH, sb + SM1_WHH_H,
                                             sb + SM1_WHH_L, acc, mrow0, ncol0, lane);
        gemm_acc<4, 128, 128, true, true, 1>(sb + rdL, sb + SM1_WHH_H, 0,
                                             acc, mrow0, ncol0, lane);

        // NO sync: epilogue writes ping-pong destination, disjoint from rd buffers
        epilogue<true>(acc, cs, sm, wrH, wrL,
                       (const float*)(sm + SM1_BIAS), mrow0, ncol0, lane);
        __syncthreads();
    }

    // LayerNorm over final h1 (hi+lo reconstruct ~fp32), one thread per sample.
    // h_{T-1} lives in buf[T&1] = buf0.
    if (tid < MT) {
        const int rdH = (T & 1) ? SM1_H1H1 : SM1_H1H0;
        const int rdL = (T & 1) ? SM1_H1L1 : SM1_H1L0;
        int row = tid;
        float hv[64];
#pragma unroll
        for (int ch = 0; ch < 8; ch++) {
            uint32_t sa = row * 128 + ((ch ^ (row & 7)) << 4);
            uint4 vh = *(uint4*)(sm + rdH + sa);
            uint4 vl = *(uint4*)(sm + rdL + sa);
            const __half2* phh = (const __half2*)&vh;
            const __half2* pll = (const __half2*)&vl;
#pragma unroll
            for (int q = 0; q < 4; q++) {
                float2 a = __half22float2(phh[q]);
                float2 b2 = __half22float2(pll[q]);
                hv[ch * 8 + 2 * q]     = a.x + b2.x;
                hv[ch * 8 + 2 * q + 1] = a.y + b2.y;
            }
        }
        float s = 0.f;
#pragma unroll
        for (int k = 0; k < 64; k++) s += hv[k];
        float mean = s * (1.f / 64.f);
        float vs = 0.f;
#pragma unroll
        for (int k = 0; k < 64; k++) { float d = hv[k] - mean; vs += d * d; }
        float rstd = rsqrtf(vs * (1.f / 64.f) + 1e-5f);
        float4* op = (float4*)(out + (size_t)(blk * MT + row) * 64);
#pragma unroll
        for (int k = 0; k < 64; k += 4) {
            float4 o;
            o.x = (hv[k + 0] - mean) * rstd * gamma[k + 0] + beta[k + 0];
            o.y = (hv[k + 1] - mean) * rstd * gamma[k + 1] + beta[k + 1];
            o.z = (hv[k + 2] - mean) * rstd * gamma[k + 2] + beta[k + 2];
            o.w = (hv[k + 3] - mean) * rstd * gamma[k + 3] + beta[k + 3];
            op[k >> 2] = o;
        }
    }
}

// =====================================================================
extern "C" void kernel_launch(void* const* d_in, const int* in_sizes, int n_in,
                              void* d_out, int out_size) {
    (void)in_sizes; (void)n_in; (void)out_size;
    const float* x     = (const float*)d_in[0];
    const float* Wih0  = (const float*)d_in[1];
    const float* Whh0  = (const float*)d_in[2];
    const float* bih0  = (const float*)d_in[3];
    const float* bhh0  = (const float*)d_in[4];
    const float* Wih1  = (const float*)d_in[5];
    const float* Whh1  = (const float*)d_in[6];
    const float* bih1  = (const float*)d_in[7];
    const float* bhh1  = (const float*)d_in[8];
    const float* gamma = (const float*)d_in[9];
    const float* beta  = (const float*)d_in[10];
    float* out = (float*)d_out;

    cudaFuncSetAttribute(k_layer0, cudaFuncAttributeMaxDynamicSharedMemorySize, SM0_TOTAL);
    cudaFuncSetAttribute(k_layer1, cudaFuncAttributeMaxDynamicSharedMemorySize, SM1_TOTAL);

    k_layer0<<<B / MT, THREADS, SM0_TOTAL>>>(x, Wih0, Whh0, bih0, bhh0);
    k_layer1<<<B / MT, THREADS, SM1_TOTAL>>>(Wih1, Whh1, bih1, bhh1, gamma, beta, out);
}